// round 11
// baseline (speedup 1.0000x reference)
#include <cstdint>
#include <cuda_runtime.h>
#include <cuda_fp16.h>
#include <math_constants.h>

// Problem constants
#define NNODES 50000
#define NEDGES 800000
#define NEALL  (NEDGES + NNODES)   // edges + self loops
#define NGRAPH 64
#define DMAX   256
#define HID    512

// ---------------- scratch (no allocations allowed) ----------------
__device__ __half g_aggh[(size_t)NNODES * 128];  // aggregated x (fp16, pre-GEMM), Din <= 128
__device__ __half g_x3h[(size_t)NNODES * DMAX];  // layer-3 output (fp16, for pooling)
__device__ __half g_xh[(size_t)NNODES * 128];    // layer-1/2 outputs (fp16 gather operand)
__device__ __half g_fh[(size_t)NNODES * 64];     // fp16 copy of input features
__device__ int    g_csr[NEALL];                  // src node per CSR slot
__device__ int    g_cnt[NNODES];                 // in-degree
__device__ int    g_off[NNODES + 1];             // CSR offsets
__device__ int    g_cursor[NNODES];              // fill cursors
__device__ float  g_as[NNODES];                  // x . (W att_src)
__device__ float  g_ad[NNODES];                  // x . (W att_dst)
__device__ float  g_wa[3 * 128];                 // W @ att_src per layer
__device__ float  g_wd[3 * 128];                 // W @ att_dst per layer
__device__ float  g_pool[NGRAPH * DMAX];         // pooled partial sums

// ---------------- CSR build ----------------
__global__ void hist_kernel(const int* __restrict__ ei, int* __restrict__ cnt) {
    int e = blockIdx.x * blockDim.x + threadIdx.x;
    if (e >= NEALL) return;
    int d = (e < NEDGES) ? ei[NEDGES + e] : (e - NEDGES);
    atomicAdd(&cnt[d], 1);
}

__global__ __launch_bounds__(1024) void scan_kernel(const int* __restrict__ cnt,
                                                    int* __restrict__ off,
                                                    int* __restrict__ cursor) {
    __shared__ int wsums[32];
    const int t = threadIdx.x;
    const int PER = (NNODES + 1023) / 1024;   // 49
    int b0 = t * PER;
    int b1 = b0 + PER; if (b1 > NNODES) b1 = NNODES;
    int s = 0;
    for (int i = b0; i < b1; i++) s += cnt[i];
    int v = s;
#pragma unroll
    for (int o = 1; o < 32; o <<= 1) {
        int n = __shfl_up_sync(0xffffffffu, v, o);
        if ((t & 31) >= o) v += n;
    }
    if ((t & 31) == 31) wsums[t >> 5] = v;
    __syncthreads();
    if (t < 32) {
        int w = wsums[t];
#pragma unroll
        for (int o = 1; o < 32; o <<= 1) {
            int n = __shfl_up_sync(0xffffffffu, w, o);
            if (t >= o) w += n;
        }
        wsums[t] = w;
    }
    __syncthreads();
    int excl = v - s + ((t >= 32) ? wsums[(t >> 5) - 1] : 0);
    int run = excl;
    for (int i = b0; i < b1; i++) {
        off[i] = run;
        cursor[i] = run;
        run += cnt[i];
    }
    if (t == 0) off[NNODES] = NEALL;
}

__global__ void csr_fill_kernel(const int* __restrict__ ei, int* __restrict__ cursor,
                                int* __restrict__ csr) {
    int e = blockIdx.x * blockDim.x + threadIdx.x;
    if (e >= NEALL) return;
    int s, d;
    if (e < NEDGES) { s = ei[e]; d = ei[NEDGES + e]; }
    else            { s = d = e - NEDGES; }
    int pos = atomicAdd(&cursor[d], 1);
    csr[pos] = s;
}

// ---------------- attention vector precompute (warp per output) ----------------
__global__ void wvec_all_kernel(const float* __restrict__ W1, const float* __restrict__ a1,
                                const float* __restrict__ W2, const float* __restrict__ a2,
                                const float* __restrict__ W3, const float* __restrict__ a3,
                                float* __restrict__ wa, float* __restrict__ wd) {
    int w = (blockIdx.x * blockDim.x + threadIdx.x) >> 5;
    int lane = threadIdx.x & 31;
    int l, idx;
    if (w < 128)      { l = 0; idx = w; }
    else if (w < 256) { l = 1; idx = w - 128; }
    else if (w < 512) { l = 2; idx = w - 256; }
    else return;
    const float* W = (l == 0) ? W1 : (l == 1) ? W2 : W3;
    const float* att = (l == 0) ? a1 : (l == 1) ? a2 : a3;
    int Din = (l == 2) ? 128 : 64;
    int Dout = (l == 0) ? 64 : (l == 1) ? 128 : 256;
    int which = (idx >= Din) ? 1 : 0;
    int i = idx - which * Din;
    const float* attp = att + which * Dout;
    const float* Wr = W + (size_t)i * Dout;
    float acc = 0.f;
    for (int d = lane; d < Dout; d += 32) acc += Wr[d] * attp[d];
#pragma unroll
    for (int o = 16; o; o >>= 1) acc += __shfl_xor_sync(0xffffffffu, acc, o);
    if (lane == 0) {
        if (which == 0) wa[l * 128 + i] = acc;
        else            wd[l * 128 + i] = acc;
    }
}

// layer-1 dots from raw features + emit fp16 feature copy (warp per node, Din=64)
__global__ void attdot_x_kernel(const float* __restrict__ x, const float* __restrict__ wa,
                                const float* __restrict__ wd,
                                float* __restrict__ as_, float* __restrict__ ad_,
                                __half* __restrict__ xh) {
    int w = (blockIdx.x * blockDim.x + threadIdx.x) >> 5;
    int lane = threadIdx.x & 31;
    if (w >= NNODES) return;
    float2 xv = *(const float2*)(x + (size_t)w * 64 + 2 * lane);
    float a0 = xv.x * wa[2 * lane] + xv.y * wa[2 * lane + 1];
    float a1 = xv.x * wd[2 * lane] + xv.y * wd[2 * lane + 1];
    *(__half2*)(xh + (size_t)w * 64 + 2 * lane) = __floats2half2_rn(xv.x, xv.y);
#pragma unroll
    for (int o = 16; o; o >>= 1) {
        a0 += __shfl_xor_sync(0xffffffffu, a0, o);
        a1 += __shfl_xor_sync(0xffffffffu, a1, o);
    }
    if (lane == 0) { as_[w] = a0; ad_[w] = a1; }
}

// ---------------- fused GAT aggregation (fp16 in, fp16 out) ----------------
// warp per dst node. Pass 1 keeps each edge's logit in a register (lane = edge
// index within segment, first 32 edges); pass 2 fetches it by shfl — the random
// as_ lookup disappears from the gather loop for deg<=32 (~all nodes).
template <int D>
__global__ __launch_bounds__(256) void gat_aggregate_kernel(
    const __half* __restrict__ x, const float* __restrict__ as_,
    const float* __restrict__ ad_, const int* __restrict__ off,
    const int* __restrict__ csr, __half* __restrict__ out) {
    int w = (blockIdx.x * blockDim.x + threadIdx.x) >> 5;
    int lane = threadIdx.x & 31;
    if (w >= NNODES) return;
    int lo = off[w], hi = off[w + 1];
    float adv = ad_[w];

    // pass 1: logits; this lane's register lv holds logit of edge lo+lane
    float lv = 0.f;
    float mx = -CUDART_INF_F;
    {
        int e = lo + lane;
        if (e < hi) {
            float v = as_[csr[e]] + adv;
            v = (v > 0.f) ? v : 0.2f * v;
            lv = v;
            mx = v;
        }
        for (e += 32; e < hi; e += 32) {
            float v = as_[csr[e]] + adv;
            v = (v > 0.f) ? v : 0.2f * v;
            mx = fmaxf(mx, v);
        }
    }
#pragma unroll
    for (int o = 16; o; o >>= 1) mx = fmaxf(mx, __shfl_xor_sync(0xffffffffu, mx, o));

    // pass 2: NEDG edges in flight; each sub-group of LPG lanes covers the row
    constexpr int NEDG = (D == 64) ? 4 : 2;
    constexpr int LPG  = 32 / NEDG;              // 8 or 16 lanes; 8 halves each
    const int sub = lane / LPG;
    const int sl  = lane % LPG;

    float2 acc[4];
#pragma unroll
    for (int k = 0; k < 4; k++) acc[k] = make_float2(0.f, 0.f);
    float ssum = 0.f;

    for (int e0 = lo; e0 < hi; e0 += NEDG) {
        int e = e0 + sub;
        bool valid = (e < hi);
        int idx = e - lo;
        // all 32 lanes execute the shfl (convergent); garbage for invalid lanes
        float lgt = __shfl_sync(0xffffffffu, lv, idx & 31);
        int s = valid ? csr[e] : 0;
        float wgt = 0.f;
        if (valid) {
            if (idx >= 32) {          // rare: degree > 32, recompute
                float v = as_[s] + adv;
                lgt = (v > 0.f) ? v : 0.2f * v;
            }
            wgt = __expf(lgt - mx);
        }
        ssum += wgt;
        if (valid) {
            uint4 raw = *(const uint4*)(x + (size_t)s * D + sl * 8);
            const __half2* hp = (const __half2*)&raw;
#pragma unroll
            for (int k = 0; k < 4; k++) {
                float2 f = __half22float2(hp[k]);
                acc[k].x += wgt * f.x;
                acc[k].y += wgt * f.y;
            }
        }
    }

    // combine sub-groups (identical feature positions)
#pragma unroll
    for (int o = LPG; o < 32; o <<= 1) {
        ssum += __shfl_xor_sync(0xffffffffu, ssum, o);
#pragma unroll
        for (int k = 0; k < 4; k++) {
            acc[k].x += __shfl_xor_sync(0xffffffffu, acc[k].x, o);
            acc[k].y += __shfl_xor_sync(0xffffffffu, acc[k].y, o);
        }
    }

    if (sub == 0) {
        float inv = 1.f / ssum;
        __half2 r[4];
#pragma unroll
        for (int k = 0; k < 4; k++)
            r[k] = __floats2half2_rn(acc[k].x * inv, acc[k].y * inv);
        *(uint4*)(out + (size_t)w * D + sl * 8) = *(const uint4*)r;
    }
}

// ---------------- FP16 tensor-core GEMM: relu(A @ B + bias) ----------------
__device__ __forceinline__ void mma_f16(float* c, const uint32_t* a, const uint32_t* b) {
    asm volatile("mma.sync.aligned.m16n8k16.row.col.f32.f16.f16.f32 "
                 "{%0,%1,%2,%3}, {%4,%5,%6,%7}, {%8,%9}, {%0,%1,%2,%3};"
                 : "+f"(c[0]), "+f"(c[1]), "+f"(c[2]), "+f"(c[3])
                 : "r"(a[0]), "r"(a[1]), "r"(a[2]), "r"(a[3]), "r"(b[0]), "r"(b[1]));
}

#define TBM 128
#define TBN 64
#define TBK 32
#define TKP (TBK + 8)   // padded row stride in halves (80B, 16B-aligned)

__global__ __launch_bounds__(256) void h16_gemm_kernel(const __half* __restrict__ A,
                                                       const float* __restrict__ B,
                                                       const float* __restrict__ bias,
                                                       __half* __restrict__ Ch,
                                                       int M, int N, int K,
                                                       const float* __restrict__ wa_next,
                                                       const float* __restrict__ wd_next,
                                                       float* __restrict__ as_,
                                                       float* __restrict__ ad_) {
    __shared__ __half As[TBM][TKP];   // row-major [m][k]
    __shared__ __half Bs[TBN][TKP];   // n-major  [n][k]
    const int tid = threadIdx.x;
    const int warp = tid >> 5, lane = tid & 31;
    const int g = lane >> 2, q = lane & 3;
    const int m0 = (warp >> 1) * 32;
    const int n0 = (warp & 1) * 32;
    const int row0 = blockIdx.x * TBM;
    const int col0 = blockIdx.y * TBN;

    float acc[2][4][4];
#pragma unroll
    for (int mt = 0; mt < 2; mt++)
#pragma unroll
        for (int nt = 0; nt < 4; nt++)
#pragma unroll
            for (int i = 0; i < 4; i++) acc[mt][nt][i] = 0.f;

    for (int k0 = 0; k0 < K; k0 += TBK) {
        // stage A: 128 rows x 32 halves; uint4 = 8 halves per thread, 2 iters
#pragma unroll
        for (int i = 0; i < 2; i++) {
            int linear = tid + 256 * i;          // 0..511
            int ar = linear >> 2;                // 0..127
            int ac = (linear & 3) << 3;          // 0,8,16,24
            int grow = row0 + ar;
            uint4 v = make_uint4(0u, 0u, 0u, 0u);
            if (grow < M) v = *(const uint4*)(A + (size_t)grow * K + k0 + ac);
            *(uint4*)&As[ar][ac] = v;
        }
        // stage B: 32 k-rows x 64 n; convert fp32->fp16, transpose to [n][k]
#pragma unroll
        for (int i = 0; i < 2; i++) {
            int linear = tid + 256 * i;          // 0..511
            int bk = linear >> 4;                // 0..31
            int bn = (linear & 15) << 2;         // 0..60
            float4 v = *(const float4*)(B + (size_t)(k0 + bk) * N + col0 + bn);
            Bs[bn + 0][bk] = __float2half_rn(v.x);
            Bs[bn + 1][bk] = __float2half_rn(v.y);
            Bs[bn + 2][bk] = __float2half_rn(v.z);
            Bs[bn + 3][bk] = __float2half_rn(v.w);
        }
        __syncthreads();
#pragma unroll
        for (int ks = 0; ks < TBK; ks += 16) {
            uint32_t af[2][4], bf[4][2];
#pragma unroll
            for (int mt = 0; mt < 2; mt++) {
                int mb = m0 + mt * 16;
                af[mt][0] = *(const uint32_t*)&As[mb + g][ks + 2 * q];
                af[mt][1] = *(const uint32_t*)&As[mb + 8 + g][ks + 2 * q];
                af[mt][2] = *(const uint32_t*)&As[mb + g][ks + 2 * q + 8];
                af[mt][3] = *(const uint32_t*)&As[mb + 8 + g][ks + 2 * q + 8];
            }
#pragma unroll
            for (int nt = 0; nt < 4; nt++) {
                int nb = n0 + nt * 8 + g;
                bf[nt][0] = *(const uint32_t*)&Bs[nb][ks + 2 * q];
                bf[nt][1] = *(const uint32_t*)&Bs[nb][ks + 2 * q + 8];
            }
#pragma unroll
            for (int mt = 0; mt < 2; mt++)
#pragma unroll
                for (int nt = 0; nt < 4; nt++)
                    mma_f16(acc[mt][nt], af[mt], bf[nt]);
        }
        __syncthreads();
    }

    // epilogue: bias + relu + fp16 store + optional fused attention dots
#pragma unroll
    for (int mt = 0; mt < 2; mt++) {
        int r0 = row0 + m0 + mt * 16 + g;
        int r1 = r0 + 8;
        float sa0 = 0.f, sd0 = 0.f, sa1 = 0.f, sd1 = 0.f;
#pragma unroll
        for (int nt = 0; nt < 4; nt++) {
            int col = col0 + n0 + nt * 8 + 2 * q;
            float b0 = bias[col], b1 = bias[col + 1];
            float v00 = fmaxf(acc[mt][nt][0] + b0, 0.f);
            float v01 = fmaxf(acc[mt][nt][1] + b1, 0.f);
            float v10 = fmaxf(acc[mt][nt][2] + b0, 0.f);
            float v11 = fmaxf(acc[mt][nt][3] + b1, 0.f);
            if (r0 < M) *(__half2*)(Ch + (size_t)r0 * N + col) = __floats2half2_rn(v00, v01);
            if (r1 < M) *(__half2*)(Ch + (size_t)r1 * N + col) = __floats2half2_rn(v10, v11);
            if (wa_next) {
                float wa0 = wa_next[col], wa1 = wa_next[col + 1];
                float wd0 = wd_next[col], wd1 = wd_next[col + 1];
                sa0 += v00 * wa0 + v01 * wa1;
                sd0 += v00 * wd0 + v01 * wd1;
                sa1 += v10 * wa0 + v11 * wa1;
                sd1 += v10 * wd0 + v11 * wd1;
            }
        }
        if (wa_next) {
#pragma unroll
            for (int o = 1; o < 4; o <<= 1) {
                sa0 += __shfl_xor_sync(0xffffffffu, sa0, o);
                sd0 += __shfl_xor_sync(0xffffffffu, sd0, o);
                sa1 += __shfl_xor_sync(0xffffffffu, sa1, o);
                sd1 += __shfl_xor_sync(0xffffffffu, sd1, o);
            }
            if (q == 0) {
                if (r0 < M) { atomicAdd(&as_[r0], sa0); atomicAdd(&ad_[r0], sd0); }
                if (r1 < M) { atomicAdd(&as_[r1], sa1); atomicAdd(&ad_[r1], sd1); }
            }
        }
    }
}

// ---------------- pooling + MLP ----------------
__device__ __forceinline__ int lbound(const int* a, int n, int key) {
    int lo = 0, hi = n;
    while (lo < hi) {
        int mid = (lo + hi) >> 1;
        if (a[mid] < key) lo = mid + 1; else hi = mid;
    }
    return lo;
}

#define POOL_SPLIT 8
__global__ void pool_partial_kernel(const __half* __restrict__ x, const int* __restrict__ batch,
                                    float* __restrict__ pool) {
    int g = blockIdx.x / POOL_SPLIT;
    int part = blockIdx.x % POOL_SPLIT;
    int t = threadIdx.x;
    int lo = lbound(batch, NNODES, g);
    int hi = lbound(batch, NNODES, g + 1);
    int seg = hi - lo;
    int a = lo + (int)(((long long)seg * part) / POOL_SPLIT);
    int b = lo + (int)(((long long)seg * (part + 1)) / POOL_SPLIT);
    float acc = 0.f;
    for (int n = a; n < b; n++) acc += __half2float(x[(size_t)n * DMAX + t]);
    if (b > a) atomicAdd(&pool[g * DMAX + t], acc);
}

__global__ void mlp_kernel(const float* __restrict__ pool, const int* __restrict__ batch,
                           const float* __restrict__ fc1w, const float* __restrict__ fc1b,
                           const float* __restrict__ fc2w, const float* __restrict__ fc2b,
                           float* __restrict__ out) {
    __shared__ float gc[DMAX];
    __shared__ float hid[HID];
    __shared__ float red[256];
    int g = blockIdx.x;
    int t = threadIdx.x;
    int lo = lbound(batch, NNODES, g);
    int hi = lbound(batch, NNODES, g + 1);
    float cnt = fmaxf((float)(hi - lo), 1.f);
    gc[t] = pool[g * DMAX + t] / cnt;
    __syncthreads();
    for (int c = t; c < HID; c += 256) {
        float a = fc1b[c];
#pragma unroll 8
        for (int k = 0; k < DMAX; k++) a += gc[k] * fc1w[(size_t)k * HID + c];
        hid[c] = fmaxf(a, 0.f);
    }
    __syncthreads();
    float p = 0.f;
    for (int c = t; c < HID; c += 256) p += hid[c] * fc2w[c];
    red[t] = p;
    __syncthreads();
    for (int s = 128; s; s >>= 1) {
        if (t < s) red[t] += red[t + s];
        __syncthreads();
    }
    if (t == 0) out[g] = red[0] + fc2b[0];
}

// ---------------- launcher ----------------
extern "C" void kernel_launch(void* const* d_in, const int* in_sizes, int n_in,
                              void* d_out, int out_size) {
    const float* feature = (const float*)d_in[0];
    const int*   ei      = (const int*)d_in[1];
    const int*   batch   = (const int*)d_in[2];
    const float* W[3]    = {(const float*)d_in[3], (const float*)d_in[6], (const float*)d_in[9]};
    const float* att[3]  = {(const float*)d_in[4], (const float*)d_in[7], (const float*)d_in[10]};
    const float* bia[3]  = {(const float*)d_in[5], (const float*)d_in[8], (const float*)d_in[11]};
    const float* fc1w    = (const float*)d_in[12];
    const float* fc1b    = (const float*)d_in[13];
    const float* fc2w    = (const float*)d_in[14];
    const float* fc2b    = (const float*)d_in[15];

    float *asbuf, *adbuf, *wabuf, *wdbuf, *pool;
    __half *aggh, *xh, *fh, *x3h;
    int *csr, *cnt, *off, *cursor;
    cudaGetSymbolAddress((void**)&aggh, g_aggh);
    cudaGetSymbolAddress((void**)&x3h, g_x3h);
    cudaGetSymbolAddress((void**)&xh, g_xh);
    cudaGetSymbolAddress((void**)&fh, g_fh);
    cudaGetSymbolAddress((void**)&csr, g_csr);
    cudaGetSymbolAddress((void**)&cnt, g_cnt);
    cudaGetSymbolAddress((void**)&off, g_off);
    cudaGetSymbolAddress((void**)&cursor, g_cursor);
    cudaGetSymbolAddress((void**)&asbuf, g_as);
    cudaGetSymbolAddress((void**)&adbuf, g_ad);
    cudaGetSymbolAddress((void**)&wabuf, g_wa);
    cudaGetSymbolAddress((void**)&wdbuf, g_wd);
    cudaGetSymbolAddress((void**)&pool, g_pool);

    // ---- build CSR (by dst) ----
    cudaMemsetAsync(cnt, 0, NNODES * sizeof(int));
    hist_kernel<<<(NEALL + 255) / 256, 256>>>(ei, cnt);
    scan_kernel<<<1, 1024>>>(cnt, off, cursor);
    csr_fill_kernel<<<(NEALL + 255) / 256, 256>>>(ei, cursor, csr);

    // ---- attention vectors for all layers ----
    wvec_all_kernel<<<64, 256>>>(W[0], att[0], W[1], att[1], W[2], att[2], wabuf, wdbuf);

    const int aggBlocks = (NNODES * 32 + 255) / 256;

    // layer 1 dots from raw features + fp16 feature copy
    attdot_x_kernel<<<aggBlocks, 256>>>(feature, wabuf, wdbuf, asbuf, adbuf, fh);

    // ---- layer 1: agg(fh, D=64) -> gemm (64->64) -> xh, fuse layer-2 dots ----
    gat_aggregate_kernel<64><<<aggBlocks, 256>>>(fh, asbuf, adbuf, off, csr, aggh);
    cudaMemsetAsync(asbuf, 0, NNODES * sizeof(float));
    cudaMemsetAsync(adbuf, 0, NNODES * sizeof(float));
    h16_gemm_kernel<<<dim3((NNODES + TBM - 1) / TBM, 64 / TBN), 256>>>(
        aggh, W[0], bia[0], xh, NNODES, 64, 64,
        wabuf + 128, wdbuf + 128, asbuf, adbuf);

    // ---- layer 2: agg(xh, D=64) -> gemm (64->128) -> xh, fuse layer-3 dots ----
    gat_aggregate_kernel<64><<<aggBlocks, 256>>>(xh, asbuf, adbuf, off, csr, aggh);
    cudaMemsetAsync(asbuf, 0, NNODES * sizeof(float));
    cudaMemsetAsync(adbuf, 0, NNODES * sizeof(float));
    h16_gemm_kernel<<<dim3((NNODES + TBM - 1) / TBM, 128 / TBN), 256>>>(
        aggh, W[1], bia[1], xh, NNODES, 128, 64,
        wabuf + 256, wdbuf + 256, asbuf, adbuf);

    // ---- layer 3: agg(xh, D=128) -> gemm (128->256) -> x3h (fp16) ----
    gat_aggregate_kernel<128><<<aggBlocks, 256>>>(xh, asbuf, adbuf, off, csr, aggh);
    h16_gemm_kernel<<<dim3((NNODES + TBM - 1) / TBM, 256 / TBN), 256>>>(
        aggh, W[2], bia[2], x3h, NNODES, 256, 128,
        nullptr, nullptr, nullptr, nullptr);

    // ---- pool + MLP ----
    cudaMemsetAsync(pool, 0, NGRAPH * DMAX * sizeof(float));
    pool_partial_kernel<<<NGRAPH * POOL_SPLIT, 256>>>(x3h, batch, pool);
    mlp_kernel<<<NGRAPH, 256>>>(pool, batch, fc1w, fc1b, fc2w, fc2b, (float*)d_out);
}

// round 12
// speedup vs baseline: 1.0388x; 1.0388x over previous
#include <cstdint>
#include <cuda_runtime.h>
#include <cuda_fp16.h>
#include <math_constants.h>

// Problem constants
#define NNODES 50000
#define NEDGES 800000
#define NEALL  (NEDGES + NNODES)   // edges + self loops
#define NGRAPH 64
#define DMAX   256
#define HID    512

// ---------------- scratch (no allocations allowed) ----------------
__device__ __half g_aggh[(size_t)NNODES * 128];  // aggregated x (fp16, pre-GEMM), Din <= 128
__device__ __half g_x3h[(size_t)NNODES * DMAX];  // layer-3 output (fp16, for pooling)
__device__ __half g_xh[(size_t)NNODES * 128];    // layer-1/2 outputs (fp16 gather operand)
__device__ __half g_fh[(size_t)NNODES * 64];     // fp16 copy of input features
__device__ int    g_csr[NEALL];                  // src node per CSR slot
__device__ int    g_cnt[NNODES];                 // in-degree
__device__ int    g_off[NNODES + 1];             // CSR offsets
__device__ int    g_cursor[NNODES];              // fill cursors
__device__ float  g_as[NNODES];                  // x . (W att_src)
__device__ float  g_ad[NNODES];                  // x . (W att_dst)
__device__ float  g_wa[3 * 128];                 // W @ att_src per layer
__device__ float  g_wd[3 * 128];                 // W @ att_dst per layer
__device__ float  g_pool[NGRAPH * DMAX];         // pooled partial sums

// ---------------- CSR build ----------------
__global__ void hist_kernel(const int* __restrict__ ei, int* __restrict__ cnt) {
    int e = blockIdx.x * blockDim.x + threadIdx.x;
    if (e >= NEALL) return;
    int d = (e < NEDGES) ? ei[NEDGES + e] : (e - NEDGES);
    atomicAdd(&cnt[d], 1);
}

__global__ __launch_bounds__(1024) void scan_kernel(const int* __restrict__ cnt,
                                                    int* __restrict__ off,
                                                    int* __restrict__ cursor) {
    __shared__ int wsums[32];
    const int t = threadIdx.x;
    const int PER = (NNODES + 1023) / 1024;   // 49
    int b0 = t * PER;
    int b1 = b0 + PER; if (b1 > NNODES) b1 = NNODES;
    int s = 0;
    for (int i = b0; i < b1; i++) s += cnt[i];
    int v = s;
#pragma unroll
    for (int o = 1; o < 32; o <<= 1) {
        int n = __shfl_up_sync(0xffffffffu, v, o);
        if ((t & 31) >= o) v += n;
    }
    if ((t & 31) == 31) wsums[t >> 5] = v;
    __syncthreads();
    if (t < 32) {
        int w = wsums[t];
#pragma unroll
        for (int o = 1; o < 32; o <<= 1) {
            int n = __shfl_up_sync(0xffffffffu, w, o);
            if (t >= o) w += n;
        }
        wsums[t] = w;
    }
    __syncthreads();
    int excl = v - s + ((t >= 32) ? wsums[(t >> 5) - 1] : 0);
    int run = excl;
    for (int i = b0; i < b1; i++) {
        off[i] = run;
        cursor[i] = run;
        run += cnt[i];
    }
    if (t == 0) off[NNODES] = NEALL;
}

__global__ void csr_fill_kernel(const int* __restrict__ ei, int* __restrict__ cursor,
                                int* __restrict__ csr) {
    int e = blockIdx.x * blockDim.x + threadIdx.x;
    if (e >= NEALL) return;
    int s, d;
    if (e < NEDGES) { s = ei[e]; d = ei[NEDGES + e]; }
    else            { s = d = e - NEDGES; }
    int pos = atomicAdd(&cursor[d], 1);
    csr[pos] = s;
}

// ---------------- attention vector precompute (warp per output) ----------------
__global__ void wvec_all_kernel(const float* __restrict__ W1, const float* __restrict__ a1,
                                const float* __restrict__ W2, const float* __restrict__ a2,
                                const float* __restrict__ W3, const float* __restrict__ a3,
                                float* __restrict__ wa, float* __restrict__ wd) {
    int w = (blockIdx.x * blockDim.x + threadIdx.x) >> 5;
    int lane = threadIdx.x & 31;
    int l, idx;
    if (w < 128)      { l = 0; idx = w; }
    else if (w < 256) { l = 1; idx = w - 128; }
    else if (w < 512) { l = 2; idx = w - 256; }
    else return;
    const float* W = (l == 0) ? W1 : (l == 1) ? W2 : W3;
    const float* att = (l == 0) ? a1 : (l == 1) ? a2 : a3;
    int Din = (l == 2) ? 128 : 64;
    int Dout = (l == 0) ? 64 : (l == 1) ? 128 : 256;
    int which = (idx >= Din) ? 1 : 0;
    int i = idx - which * Din;
    const float* attp = att + which * Dout;
    const float* Wr = W + (size_t)i * Dout;
    float acc = 0.f;
    for (int d = lane; d < Dout; d += 32) acc += Wr[d] * attp[d];
#pragma unroll
    for (int o = 16; o; o >>= 1) acc += __shfl_xor_sync(0xffffffffu, acc, o);
    if (lane == 0) {
        if (which == 0) wa[l * 128 + i] = acc;
        else            wd[l * 128 + i] = acc;
    }
}

// layer-1 dots from raw features + emit fp16 feature copy (warp per node, Din=64)
__global__ void attdot_x_kernel(const float* __restrict__ x, const float* __restrict__ wa,
                                const float* __restrict__ wd,
                                float* __restrict__ as_, float* __restrict__ ad_,
                                __half* __restrict__ xh) {
    int w = (blockIdx.x * blockDim.x + threadIdx.x) >> 5;
    int lane = threadIdx.x & 31;
    if (w >= NNODES) return;
    float2 xv = *(const float2*)(x + (size_t)w * 64 + 2 * lane);
    float a0 = xv.x * wa[2 * lane] + xv.y * wa[2 * lane + 1];
    float a1 = xv.x * wd[2 * lane] + xv.y * wd[2 * lane + 1];
    *(__half2*)(xh + (size_t)w * 64 + 2 * lane) = __floats2half2_rn(xv.x, xv.y);
#pragma unroll
    for (int o = 16; o; o >>= 1) {
        a0 += __shfl_xor_sync(0xffffffffu, a0, o);
        a1 += __shfl_xor_sync(0xffffffffu, a1, o);
    }
    if (lane == 0) { as_[w] = a0; ad_[w] = a1; }
}

// ---------------- fused GAT aggregation (fp16 in, fp16 out) ----------------
// warp per dst node; NEDG edges in flight; each lane loads 8 halves (16B).
// Pass 2 uses the direct as_ lookup (round-10 shape — measured optimum).
template <int D>
__global__ __launch_bounds__(256) void gat_aggregate_kernel(
    const __half* __restrict__ x, const float* __restrict__ as_,
    const float* __restrict__ ad_, const int* __restrict__ off,
    const int* __restrict__ csr, __half* __restrict__ out) {
    int w = (blockIdx.x * blockDim.x + threadIdx.x) >> 5;
    int lane = threadIdx.x & 31;
    if (w >= NNODES) return;
    int lo = off[w], hi = off[w + 1];
    float adv = ad_[w];

    // pass 1: segment max of leaky_relu(as[src]+ad[dst])
    float mx = -CUDART_INF_F;
    for (int e = lo + lane; e < hi; e += 32) {
        float v = as_[csr[e]] + adv;
        v = (v > 0.f) ? v : 0.2f * v;
        mx = fmaxf(mx, v);
    }
#pragma unroll
    for (int o = 16; o; o >>= 1) mx = fmaxf(mx, __shfl_xor_sync(0xffffffffu, mx, o));

    // pass 2: NEDG edges in flight; each sub-group of LPG lanes covers the row
    constexpr int NEDG = (D == 64) ? 4 : 2;
    constexpr int LPG  = 32 / NEDG;              // 8 or 16 lanes; 8 halves each
    const int sub = lane / LPG;
    const int sl  = lane % LPG;

    float2 acc[4];
#pragma unroll
    for (int k = 0; k < 4; k++) acc[k] = make_float2(0.f, 0.f);
    float ssum = 0.f;

    for (int e0 = lo; e0 < hi; e0 += NEDG) {
        int e = e0 + sub;
        bool valid = (e < hi);
        int s = valid ? csr[e] : 0;
        float wgt = 0.f;
        if (valid) {
            float v = as_[s] + adv;
            v = (v > 0.f) ? v : 0.2f * v;
            wgt = __expf(v - mx);
        }
        ssum += wgt;
        if (valid) {
            uint4 raw = *(const uint4*)(x + (size_t)s * D + sl * 8);
            const __half2* hp = (const __half2*)&raw;
#pragma unroll
            for (int k = 0; k < 4; k++) {
                float2 f = __half22float2(hp[k]);
                acc[k].x += wgt * f.x;
                acc[k].y += wgt * f.y;
            }
        }
    }

    // combine sub-groups (identical feature positions)
#pragma unroll
    for (int o = LPG; o < 32; o <<= 1) {
        ssum += __shfl_xor_sync(0xffffffffu, ssum, o);
#pragma unroll
        for (int k = 0; k < 4; k++) {
            acc[k].x += __shfl_xor_sync(0xffffffffu, acc[k].x, o);
            acc[k].y += __shfl_xor_sync(0xffffffffu, acc[k].y, o);
        }
    }

    if (sub == 0) {
        float inv = 1.f / ssum;
        __half2 r[4];
#pragma unroll
        for (int k = 0; k < 4; k++)
            r[k] = __floats2half2_rn(acc[k].x * inv, acc[k].y * inv);
        *(uint4*)(out + (size_t)w * D + sl * 8) = *(const uint4*)r;
    }
}

// ---------------- FP16 tensor-core GEMM: relu(A @ B + bias) ----------------
__device__ __forceinline__ void mma_f16(float* c, const uint32_t* a, const uint32_t* b) {
    asm volatile("mma.sync.aligned.m16n8k16.row.col.f32.f16.f16.f32 "
                 "{%0,%1,%2,%3}, {%4,%5,%6,%7}, {%8,%9}, {%0,%1,%2,%3};"
                 : "+f"(c[0]), "+f"(c[1]), "+f"(c[2]), "+f"(c[3])
                 : "r"(a[0]), "r"(a[1]), "r"(a[2]), "r"(a[3]), "r"(b[0]), "r"(b[1]));
}

#define TBM 128
#define TBN 64
#define TBK 32
#define TKP (TBK + 8)   // padded row stride in halves (80B, 16B-aligned)

__global__ __launch_bounds__(256) void h16_gemm_kernel(const __half* __restrict__ A,
                                                       const float* __restrict__ B,
                                                       const float* __restrict__ bias,
                                                       __half* __restrict__ Ch,
                                                       int M, int N, int K,
                                                       const float* __restrict__ wa_next,
                                                       const float* __restrict__ wd_next,
                                                       float* __restrict__ as_,
                                                       float* __restrict__ ad_) {
    __shared__ __half As[TBM][TKP];   // row-major [m][k]
    __shared__ __half Bs[TBN][TKP];   // n-major  [n][k]
    const int tid = threadIdx.x;
    const int warp = tid >> 5, lane = tid & 31;
    const int g = lane >> 2, q = lane & 3;
    const int m0 = (warp >> 1) * 32;
    const int n0 = (warp & 1) * 32;
    const int row0 = blockIdx.x * TBM;
    const int col0 = blockIdx.y * TBN;

    float acc[2][4][4];
#pragma unroll
    for (int mt = 0; mt < 2; mt++)
#pragma unroll
        for (int nt = 0; nt < 4; nt++)
#pragma unroll
            for (int i = 0; i < 4; i++) acc[mt][nt][i] = 0.f;

    for (int k0 = 0; k0 < K; k0 += TBK) {
        // stage A: 128 rows x 32 halves; uint4 = 8 halves per thread, 2 iters
#pragma unroll
        for (int i = 0; i < 2; i++) {
            int linear = tid + 256 * i;          // 0..511
            int ar = linear >> 2;                // 0..127
            int ac = (linear & 3) << 3;          // 0,8,16,24
            int grow = row0 + ar;
            uint4 v = make_uint4(0u, 0u, 0u, 0u);
            if (grow < M) v = *(const uint4*)(A + (size_t)grow * K + k0 + ac);
            *(uint4*)&As[ar][ac] = v;
        }
        // stage B: 32 k-rows x 64 n; convert fp32->fp16, transpose to [n][k]
#pragma unroll
        for (int i = 0; i < 2; i++) {
            int linear = tid + 256 * i;          // 0..511
            int bk = linear >> 4;                // 0..31
            int bn = (linear & 15) << 2;         // 0..60
            float4 v = *(const float4*)(B + (size_t)(k0 + bk) * N + col0 + bn);
            Bs[bn + 0][bk] = __float2half_rn(v.x);
            Bs[bn + 1][bk] = __float2half_rn(v.y);
            Bs[bn + 2][bk] = __float2half_rn(v.z);
            Bs[bn + 3][bk] = __float2half_rn(v.w);
        }
        __syncthreads();
#pragma unroll
        for (int ks = 0; ks < TBK; ks += 16) {
            uint32_t af[2][4], bf[4][2];
#pragma unroll
            for (int mt = 0; mt < 2; mt++) {
                int mb = m0 + mt * 16;
                af[mt][0] = *(const uint32_t*)&As[mb + g][ks + 2 * q];
                af[mt][1] = *(const uint32_t*)&As[mb + 8 + g][ks + 2 * q];
                af[mt][2] = *(const uint32_t*)&As[mb + g][ks + 2 * q + 8];
                af[mt][3] = *(const uint32_t*)&As[mb + 8 + g][ks + 2 * q + 8];
            }
#pragma unroll
            for (int nt = 0; nt < 4; nt++) {
                int nb = n0 + nt * 8 + g;
                bf[nt][0] = *(const uint32_t*)&Bs[nb][ks + 2 * q];
                bf[nt][1] = *(const uint32_t*)&Bs[nb][ks + 2 * q + 8];
            }
#pragma unroll
            for (int mt = 0; mt < 2; mt++)
#pragma unroll
                for (int nt = 0; nt < 4; nt++)
                    mma_f16(acc[mt][nt], af[mt], bf[nt]);
        }
        __syncthreads();
    }

    // epilogue: bias + relu + fp16 store + optional fused attention dots
#pragma unroll
    for (int mt = 0; mt < 2; mt++) {
        int r0 = row0 + m0 + mt * 16 + g;
        int r1 = r0 + 8;
        float sa0 = 0.f, sd0 = 0.f, sa1 = 0.f, sd1 = 0.f;
#pragma unroll
        for (int nt = 0; nt < 4; nt++) {
            int col = col0 + n0 + nt * 8 + 2 * q;
            float b0 = bias[col], b1 = bias[col + 1];
            float v00 = fmaxf(acc[mt][nt][0] + b0, 0.f);
            float v01 = fmaxf(acc[mt][nt][1] + b1, 0.f);
            float v10 = fmaxf(acc[mt][nt][2] + b0, 0.f);
            float v11 = fmaxf(acc[mt][nt][3] + b1, 0.f);
            if (r0 < M) *(__half2*)(Ch + (size_t)r0 * N + col) = __floats2half2_rn(v00, v01);
            if (r1 < M) *(__half2*)(Ch + (size_t)r1 * N + col) = __floats2half2_rn(v10, v11);
            if (wa_next) {
                float wa0 = wa_next[col], wa1 = wa_next[col + 1];
                float wd0 = wd_next[col], wd1 = wd_next[col + 1];
                sa0 += v00 * wa0 + v01 * wa1;
                sd0 += v00 * wd0 + v01 * wd1;
                sa1 += v10 * wa0 + v11 * wa1;
                sd1 += v10 * wd0 + v11 * wd1;
            }
        }
        if (wa_next) {
#pragma unroll
            for (int o = 1; o < 4; o <<= 1) {
                sa0 += __shfl_xor_sync(0xffffffffu, sa0, o);
                sd0 += __shfl_xor_sync(0xffffffffu, sd0, o);
                sa1 += __shfl_xor_sync(0xffffffffu, sa1, o);
                sd1 += __shfl_xor_sync(0xffffffffu, sd1, o);
            }
            if (q == 0) {
                if (r0 < M) { atomicAdd(&as_[r0], sa0); atomicAdd(&ad_[r0], sd0); }
                if (r1 < M) { atomicAdd(&as_[r1], sa1); atomicAdd(&ad_[r1], sd1); }
            }
        }
    }
}

// ---------------- pooling + MLP ----------------
__device__ __forceinline__ int lbound(const int* a, int n, int key) {
    int lo = 0, hi = n;
    while (lo < hi) {
        int mid = (lo + hi) >> 1;
        if (a[mid] < key) lo = mid + 1; else hi = mid;
    }
    return lo;
}

#define POOL_SPLIT 8
__global__ void pool_partial_kernel(const __half* __restrict__ x, const int* __restrict__ batch,
                                    float* __restrict__ pool) {
    int g = blockIdx.x / POOL_SPLIT;
    int part = blockIdx.x % POOL_SPLIT;
    int t = threadIdx.x;
    int lo = lbound(batch, NNODES, g);
    int hi = lbound(batch, NNODES, g + 1);
    int seg = hi - lo;
    int a = lo + (int)(((long long)seg * part) / POOL_SPLIT);
    int b = lo + (int)(((long long)seg * (part + 1)) / POOL_SPLIT);
    float acc = 0.f;
    for (int n = a; n < b; n++) acc += __half2float(x[(size_t)n * DMAX + t]);
    if (b > a) atomicAdd(&pool[g * DMAX + t], acc);
}

__global__ void mlp_kernel(const float* __restrict__ pool, const int* __restrict__ batch,
                           const float* __restrict__ fc1w, const float* __restrict__ fc1b,
                           const float* __restrict__ fc2w, const float* __restrict__ fc2b,
                           float* __restrict__ out) {
    __shared__ float gc[DMAX];
    __shared__ float hid[HID];
    __shared__ float red[256];
    int g = blockIdx.x;
    int t = threadIdx.x;
    int lo = lbound(batch, NNODES, g);
    int hi = lbound(batch, NNODES, g + 1);
    float cnt = fmaxf((float)(hi - lo), 1.f);
    gc[t] = pool[g * DMAX + t] / cnt;
    __syncthreads();
    for (int c = t; c < HID; c += 256) {
        float a = fc1b[c];
#pragma unroll 8
        for (int k = 0; k < DMAX; k++) a += gc[k] * fc1w[(size_t)k * HID + c];
        hid[c] = fmaxf(a, 0.f);
    }
    __syncthreads();
    float p = 0.f;
    for (int c = t; c < HID; c += 256) p += hid[c] * fc2w[c];
    red[t] = p;
    __syncthreads();
    for (int s = 128; s; s >>= 1) {
        if (t < s) red[t] += red[t + s];
        __syncthreads();
    }
    if (t == 0) out[g] = red[0] + fc2b[0];
}

// ---------------- launcher ----------------
extern "C" void kernel_launch(void* const* d_in, const int* in_sizes, int n_in,
                              void* d_out, int out_size) {
    const float* feature = (const float*)d_in[0];
    const int*   ei      = (const int*)d_in[1];
    const int*   batch   = (const int*)d_in[2];
    const float* W[3]    = {(const float*)d_in[3], (const float*)d_in[6], (const float*)d_in[9]};
    const float* att[3]  = {(const float*)d_in[4], (const float*)d_in[7], (const float*)d_in[10]};
    const float* bia[3]  = {(const float*)d_in[5], (const float*)d_in[8], (const float*)d_in[11]};
    const float* fc1w    = (const float*)d_in[12];
    const float* fc1b    = (const float*)d_in[13];
    const float* fc2w    = (const float*)d_in[14];
    const float* fc2b    = (const float*)d_in[15];

    float *asbuf, *adbuf, *wabuf, *wdbuf, *pool;
    __half *aggh, *xh, *fh, *x3h;
    int *csr, *cnt, *off, *cursor;
    cudaGetSymbolAddress((void**)&aggh, g_aggh);
    cudaGetSymbolAddress((void**)&x3h, g_x3h);
    cudaGetSymbolAddress((void**)&xh, g_xh);
    cudaGetSymbolAddress((void**)&fh, g_fh);
    cudaGetSymbolAddress((void**)&csr, g_csr);
    cudaGetSymbolAddress((void**)&cnt, g_cnt);
    cudaGetSymbolAddress((void**)&off, g_off);
    cudaGetSymbolAddress((void**)&cursor, g_cursor);
    cudaGetSymbolAddress((void**)&asbuf, g_as);
    cudaGetSymbolAddress((void**)&adbuf, g_ad);
    cudaGetSymbolAddress((void**)&wabuf, g_wa);
    cudaGetSymbolAddress((void**)&wdbuf, g_wd);
    cudaGetSymbolAddress((void**)&pool, g_pool);

    // ---- build CSR (by dst) ----
    cudaMemsetAsync(cnt, 0, NNODES * sizeof(int));
    hist_kernel<<<(NEALL + 255) / 256, 256>>>(ei, cnt);
    scan_kernel<<<1, 1024>>>(cnt, off, cursor);
    csr_fill_kernel<<<(NEALL + 255) / 256, 256>>>(ei, cursor, csr);

    // ---- attention vectors for all layers ----
    wvec_all_kernel<<<64, 256>>>(W[0], att[0], W[1], att[1], W[2], att[2], wabuf, wdbuf);

    const int aggBlocks = (NNODES * 32 + 255) / 256;

    // layer 1 dots from raw features + fp16 feature copy
    attdot_x_kernel<<<aggBlocks, 256>>>(feature, wabuf, wdbuf, asbuf, adbuf, fh);

    // ---- layer 1: agg(fh, D=64) -> gemm (64->64) -> xh, fuse layer-2 dots ----
    gat_aggregate_kernel<64><<<aggBlocks, 256>>>(fh, asbuf, adbuf, off, csr, aggh);
    cudaMemsetAsync(asbuf, 0, NNODES * sizeof(float));
    cudaMemsetAsync(adbuf, 0, NNODES * sizeof(float));
    h16_gemm_kernel<<<dim3((NNODES + TBM - 1) / TBM, 64 / TBN), 256>>>(
        aggh, W[0], bia[0], xh, NNODES, 64, 64,
        wabuf + 128, wdbuf + 128, asbuf, adbuf);

    // ---- layer 2: agg(xh, D=64) -> gemm (64->128) -> xh, fuse layer-3 dots ----
    gat_aggregate_kernel<64><<<aggBlocks, 256>>>(xh, asbuf, adbuf, off, csr, aggh);
    cudaMemsetAsync(asbuf, 0, NNODES * sizeof(float));
    cudaMemsetAsync(adbuf, 0, NNODES * sizeof(float));
    h16_gemm_kernel<<<dim3((NNODES + TBM - 1) / TBM, 128 / TBN), 256>>>(
        aggh, W[1], bia[1], xh, NNODES, 128, 64,
        wabuf + 256, wdbuf + 256, asbuf, adbuf);

    // ---- layer 3: agg(xh, D=128) -> gemm (128->256) -> x3h (fp16) ----
    gat_aggregate_kernel<128><<<aggBlocks, 256>>>(xh, asbuf, adbuf, off, csr, aggh);
    h16_gemm_kernel<<<dim3((NNODES + TBM - 1) / TBM, 256 / TBN), 256>>>(
        aggh, W[2], bia[2], x3h, NNODES, 256, 128,
        nullptr, nullptr, nullptr, nullptr);

    // ---- pool + MLP ----
    cudaMemsetAsync(pool, 0, NGRAPH * DMAX * sizeof(float));
    pool_partial_kernel<<<NGRAPH * POOL_SPLIT, 256>>>(x3h, batch, pool);
    mlp_kernel<<<NGRAPH, 256>>>(pool, batch, fc1w, fc1b, fc2w, fc2b, (float*)d_out);
}

// round 13
// speedup vs baseline: 1.1290x; 1.0868x over previous
#include <cstdint>
#include <cuda_runtime.h>
#include <cuda_fp16.h>
#include <math_constants.h>

// Problem constants
#define NNODES 50000
#define NEDGES 800000
#define NEALL  (NEDGES + NNODES)   // edges + self loops
#define NGRAPH 64
#define DMAX   256
#define HID    512

// ---------------- scratch (no allocations allowed) ----------------
__device__ __half g_aggh[(size_t)NNODES * 128];  // aggregated x (fp16, pre-GEMM)
__device__ __half g_x3h[(size_t)NNODES * DMAX];  // layer-3 output (fp16, for pooling)
__device__ __half g_xh[(size_t)NNODES * 128];    // layer-1/2 outputs (fp16 gather operand)
__device__ __half g_fh[(size_t)NNODES * 64];     // fp16 copy of input features
__device__ int    g_csr[NEALL];                  // src node per CSR slot
__device__ int    g_cnt[NNODES];                 // in-degree
__device__ int    g_off[NNODES + 1];             // CSR offsets
__device__ int    g_cursor[NNODES];              // fill cursors
__device__ float  g_asad[2 * NNODES];            // [as | ad] combined (one memset)
__device__ float  g_wa[3 * 128];                 // W @ att_src per layer
__device__ float  g_wd[3 * 128];                 // W @ att_dst per layer
__device__ float  g_pool[NGRAPH * DMAX];         // pooled partial sums

// ---------------- wvec + zero(cnt,pool): launch #1 ----------------
// 64 blocks x 256 = 512 warps for wvec; same threads zero cnt and pool.
__global__ void wvec_all_kernel(const float* __restrict__ W1, const float* __restrict__ a1,
                                const float* __restrict__ W2, const float* __restrict__ a2,
                                const float* __restrict__ W3, const float* __restrict__ a3,
                                float* __restrict__ wa, float* __restrict__ wd,
                                int* __restrict__ cnt, float* __restrict__ pool) {
    int gtid = blockIdx.x * 256 + threadIdx.x;   // 0..16383
    for (int i = gtid; i < NNODES; i += 64 * 256) cnt[i] = 0;
    for (int i = gtid; i < NGRAPH * DMAX; i += 64 * 256) pool[i] = 0.f;

    int w = gtid >> 5;
    int lane = threadIdx.x & 31;
    int l, idx;
    if (w < 128)      { l = 0; idx = w; }
    else if (w < 256) { l = 1; idx = w - 128; }
    else if (w < 512) { l = 2; idx = w - 256; }
    else return;
    const float* W = (l == 0) ? W1 : (l == 1) ? W2 : W3;
    const float* att = (l == 0) ? a1 : (l == 1) ? a2 : a3;
    int Din = (l == 2) ? 128 : 64;
    int Dout = (l == 0) ? 64 : (l == 1) ? 128 : 256;
    int which = (idx >= Din) ? 1 : 0;
    int i = idx - which * Din;
    const float* attp = att + which * Dout;
    const float* Wr = W + (size_t)i * Dout;
    float acc = 0.f;
    for (int d = lane; d < Dout; d += 32) acc += Wr[d] * attp[d];
#pragma unroll
    for (int o = 16; o; o >>= 1) acc += __shfl_xor_sync(0xffffffffu, acc, o);
    if (lane == 0) {
        if (which == 0) wa[l * 128 + i] = acc;
        else            wd[l * 128 + i] = acc;
    }
}

// ---------------- hist + layer-1 attdot + fp16 feature copy: launch #2 ----------------
#define HISTB ((NEALL + 255) / 256)      // 3321 blocks for hist
#define ATTB  ((NNODES * 32 + 255) / 256) // 6250 blocks for attdot
__global__ void hist_attdot_kernel(const int* __restrict__ ei, int* __restrict__ cnt,
                                   const float* __restrict__ x, const float* __restrict__ wa,
                                   const float* __restrict__ wd,
                                   float* __restrict__ as_, float* __restrict__ ad_,
                                   __half* __restrict__ xh) {
    if (blockIdx.x < HISTB) {
        int e = blockIdx.x * 256 + threadIdx.x;
        if (e >= NEALL) return;
        int d = (e < NEDGES) ? ei[NEDGES + e] : (e - NEDGES);
        atomicAdd(&cnt[d], 1);
    } else {
        int w = ((blockIdx.x - HISTB) * 256 + threadIdx.x) >> 5;
        int lane = threadIdx.x & 31;
        if (w >= NNODES) return;
        float2 xv = *(const float2*)(x + (size_t)w * 64 + 2 * lane);
        float a0 = xv.x * wa[2 * lane] + xv.y * wa[2 * lane + 1];
        float a1 = xv.x * wd[2 * lane] + xv.y * wd[2 * lane + 1];
        *(__half2*)(xh + (size_t)w * 64 + 2 * lane) = __floats2half2_rn(xv.x, xv.y);
#pragma unroll
        for (int o = 16; o; o >>= 1) {
            a0 += __shfl_xor_sync(0xffffffffu, a0, o);
            a1 += __shfl_xor_sync(0xffffffffu, a1, o);
        }
        if (lane == 0) { as_[w] = a0; ad_[w] = a1; }
    }
}

// ---------------- scan: launch #3 ----------------
__global__ __launch_bounds__(1024) void scan_kernel(const int* __restrict__ cnt,
                                                    int* __restrict__ off,
                                                    int* __restrict__ cursor) {
    __shared__ int wsums[32];
    const int t = threadIdx.x;
    const int PER = (NNODES + 1023) / 1024;   // 49
    int b0 = t * PER;
    int b1 = b0 + PER; if (b1 > NNODES) b1 = NNODES;
    int s = 0;
    for (int i = b0; i < b1; i++) s += cnt[i];
    int v = s;
#pragma unroll
    for (int o = 1; o < 32; o <<= 1) {
        int n = __shfl_up_sync(0xffffffffu, v, o);
        if ((t & 31) >= o) v += n;
    }
    if ((t & 31) == 31) wsums[t >> 5] = v;
    __syncthreads();
    if (t < 32) {
        int w = wsums[t];
#pragma unroll
        for (int o = 1; o < 32; o <<= 1) {
            int n = __shfl_up_sync(0xffffffffu, w, o);
            if (t >= o) w += n;
        }
        wsums[t] = w;
    }
    __syncthreads();
    int excl = v - s + ((t >= 32) ? wsums[(t >> 5) - 1] : 0);
    int run = excl;
    for (int i = b0; i < b1; i++) {
        off[i] = run;
        cursor[i] = run;
        run += cnt[i];
    }
    if (t == 0) off[NNODES] = NEALL;
}

// ---------------- csr fill: launch #4 ----------------
__global__ void csr_fill_kernel(const int* __restrict__ ei, int* __restrict__ cursor,
                                int* __restrict__ csr) {
    int e = blockIdx.x * blockDim.x + threadIdx.x;
    if (e >= NEALL) return;
    int s, d;
    if (e < NEDGES) { s = ei[e]; d = ei[NEDGES + e]; }
    else            { s = d = e - NEDGES; }
    int pos = atomicAdd(&cursor[d], 1);
    csr[pos] = s;
}

// ---------------- fused GAT aggregation (fp16 in, fp16 out): launch #5... ----------------
template <int D>
__global__ __launch_bounds__(256) void gat_aggregate_kernel(
    const __half* __restrict__ x, const float* __restrict__ as_,
    const float* __restrict__ ad_, const int* __restrict__ off,
    const int* __restrict__ csr, __half* __restrict__ out) {
    int w = (blockIdx.x * blockDim.x + threadIdx.x) >> 5;
    int lane = threadIdx.x & 31;
    if (w >= NNODES) return;
    int lo = off[w], hi = off[w + 1];
    float adv = ad_[w];

    // pass 1: segment max of leaky_relu(as[src]+ad[dst])
    float mx = -CUDART_INF_F;
    for (int e = lo + lane; e < hi; e += 32) {
        float v = as_[csr[e]] + adv;
        v = (v > 0.f) ? v : 0.2f * v;
        mx = fmaxf(mx, v);
    }
#pragma unroll
    for (int o = 16; o; o >>= 1) mx = fmaxf(mx, __shfl_xor_sync(0xffffffffu, mx, o));

    // pass 2: NEDG edges in flight; each sub-group of LPG lanes covers the row
    constexpr int NEDG = (D == 64) ? 4 : 2;
    constexpr int LPG  = 32 / NEDG;
    const int sub = lane / LPG;
    const int sl  = lane % LPG;

    float2 acc[4];
#pragma unroll
    for (int k = 0; k < 4; k++) acc[k] = make_float2(0.f, 0.f);
    float ssum = 0.f;

    for (int e0 = lo; e0 < hi; e0 += NEDG) {
        int e = e0 + sub;
        bool valid = (e < hi);
        int s = valid ? csr[e] : 0;
        float wgt = 0.f;
        if (valid) {
            float v = as_[s] + adv;
            v = (v > 0.f) ? v : 0.2f * v;
            wgt = __expf(v - mx);
        }
        ssum += wgt;
        if (valid) {
            uint4 raw = *(const uint4*)(x + (size_t)s * D + sl * 8);
            const __half2* hp = (const __half2*)&raw;
#pragma unroll
            for (int k = 0; k < 4; k++) {
                float2 f = __half22float2(hp[k]);
                acc[k].x += wgt * f.x;
                acc[k].y += wgt * f.y;
            }
        }
    }

#pragma unroll
    for (int o = LPG; o < 32; o <<= 1) {
        ssum += __shfl_xor_sync(0xffffffffu, ssum, o);
#pragma unroll
        for (int k = 0; k < 4; k++) {
            acc[k].x += __shfl_xor_sync(0xffffffffu, acc[k].x, o);
            acc[k].y += __shfl_xor_sync(0xffffffffu, acc[k].y, o);
        }
    }

    if (sub == 0) {
        float inv = 1.f / ssum;
        __half2 r[4];
#pragma unroll
        for (int k = 0; k < 4; k++)
            r[k] = __floats2half2_rn(acc[k].x * inv, acc[k].y * inv);
        *(uint4*)(out + (size_t)w * D + sl * 8) = *(const uint4*)r;
    }
}

// ---------------- FP16 tensor-core GEMM: relu(A @ B + bias) ----------------
__device__ __forceinline__ void mma_f16(float* c, const uint32_t* a, const uint32_t* b) {
    asm volatile("mma.sync.aligned.m16n8k16.row.col.f32.f16.f16.f32 "
                 "{%0,%1,%2,%3}, {%4,%5,%6,%7}, {%8,%9}, {%0,%1,%2,%3};"
                 : "+f"(c[0]), "+f"(c[1]), "+f"(c[2]), "+f"(c[3])
                 : "r"(a[0]), "r"(a[1]), "r"(a[2]), "r"(a[3]), "r"(b[0]), "r"(b[1]));
}

#define TBM 128
#define TBN 64
#define TBK 32
#define TKP (TBK + 8)   // padded row stride in halves (80B, 16B-aligned)

__global__ __launch_bounds__(256) void h16_gemm_kernel(const __half* __restrict__ A,
                                                       const float* __restrict__ B,
                                                       const float* __restrict__ bias,
                                                       __half* __restrict__ Ch,
                                                       int M, int N, int K,
                                                       const float* __restrict__ wa_next,
                                                       const float* __restrict__ wd_next,
                                                       float* __restrict__ as_,
                                                       float* __restrict__ ad_) {
    __shared__ __half As[TBM][TKP];   // row-major [m][k]
    __shared__ __half Bs[TBN][TKP];   // n-major  [n][k]
    const int tid = threadIdx.x;
    const int warp = tid >> 5, lane = tid & 31;
    const int g = lane >> 2, q = lane & 3;
    const int m0 = (warp >> 1) * 32;
    const int n0 = (warp & 1) * 32;
    const int row0 = blockIdx.x * TBM;
    const int col0 = blockIdx.y * TBN;

    float acc[2][4][4];
#pragma unroll
    for (int mt = 0; mt < 2; mt++)
#pragma unroll
        for (int nt = 0; nt < 4; nt++)
#pragma unroll
            for (int i = 0; i < 4; i++) acc[mt][nt][i] = 0.f;

    for (int k0 = 0; k0 < K; k0 += TBK) {
#pragma unroll
        for (int i = 0; i < 2; i++) {
            int linear = tid + 256 * i;
            int ar = linear >> 2;
            int ac = (linear & 3) << 3;
            int grow = row0 + ar;
            uint4 v = make_uint4(0u, 0u, 0u, 0u);
            if (grow < M) v = *(const uint4*)(A + (size_t)grow * K + k0 + ac);
            *(uint4*)&As[ar][ac] = v;
        }
#pragma unroll
        for (int i = 0; i < 2; i++) {
            int linear = tid + 256 * i;
            int bk = linear >> 4;
            int bn = (linear & 15) << 2;
            float4 v = *(const float4*)(B + (size_t)(k0 + bk) * N + col0 + bn);
            Bs[bn + 0][bk] = __float2half_rn(v.x);
            Bs[bn + 1][bk] = __float2half_rn(v.y);
            Bs[bn + 2][bk] = __float2half_rn(v.z);
            Bs[bn + 3][bk] = __float2half_rn(v.w);
        }
        __syncthreads();
#pragma unroll
        for (int ks = 0; ks < TBK; ks += 16) {
            uint32_t af[2][4], bf[4][2];
#pragma unroll
            for (int mt = 0; mt < 2; mt++) {
                int mb = m0 + mt * 16;
                af[mt][0] = *(const uint32_t*)&As[mb + g][ks + 2 * q];
                af[mt][1] = *(const uint32_t*)&As[mb + 8 + g][ks + 2 * q];
                af[mt][2] = *(const uint32_t*)&As[mb + g][ks + 2 * q + 8];
                af[mt][3] = *(const uint32_t*)&As[mb + 8 + g][ks + 2 * q + 8];
            }
#pragma unroll
            for (int nt = 0; nt < 4; nt++) {
                int nb = n0 + nt * 8 + g;
                bf[nt][0] = *(const uint32_t*)&Bs[nb][ks + 2 * q];
                bf[nt][1] = *(const uint32_t*)&Bs[nb][ks + 2 * q + 8];
            }
#pragma unroll
            for (int mt = 0; mt < 2; mt++)
#pragma unroll
                for (int nt = 0; nt < 4; nt++)
                    mma_f16(acc[mt][nt], af[mt], bf[nt]);
        }
        __syncthreads();
    }

    // epilogue: bias + relu + fp16 store + optional fused attention dots
#pragma unroll
    for (int mt = 0; mt < 2; mt++) {
        int r0 = row0 + m0 + mt * 16 + g;
        int r1 = r0 + 8;
        float sa0 = 0.f, sd0 = 0.f, sa1 = 0.f, sd1 = 0.f;
#pragma unroll
        for (int nt = 0; nt < 4; nt++) {
            int col = col0 + n0 + nt * 8 + 2 * q;
            float b0 = bias[col], b1 = bias[col + 1];
            float v00 = fmaxf(acc[mt][nt][0] + b0, 0.f);
            float v01 = fmaxf(acc[mt][nt][1] + b1, 0.f);
            float v10 = fmaxf(acc[mt][nt][2] + b0, 0.f);
            float v11 = fmaxf(acc[mt][nt][3] + b1, 0.f);
            if (r0 < M) *(__half2*)(Ch + (size_t)r0 * N + col) = __floats2half2_rn(v00, v01);
            if (r1 < M) *(__half2*)(Ch + (size_t)r1 * N + col) = __floats2half2_rn(v10, v11);
            if (wa_next) {
                float wa0 = wa_next[col], wa1 = wa_next[col + 1];
                float wd0 = wd_next[col], wd1 = wd_next[col + 1];
                sa0 += v00 * wa0 + v01 * wa1;
                sd0 += v00 * wd0 + v01 * wd1;
                sa1 += v10 * wa0 + v11 * wa1;
                sd1 += v10 * wd0 + v11 * wd1;
            }
        }
        if (wa_next) {
#pragma unroll
            for (int o = 1; o < 4; o <<= 1) {
                sa0 += __shfl_xor_sync(0xffffffffu, sa0, o);
                sd0 += __shfl_xor_sync(0xffffffffu, sd0, o);
                sa1 += __shfl_xor_sync(0xffffffffu, sa1, o);
                sd1 += __shfl_xor_sync(0xffffffffu, sd1, o);
            }
            if (q == 0) {
                if (r0 < M) { atomicAdd(&as_[r0], sa0); atomicAdd(&ad_[r0], sd0); }
                if (r1 < M) { atomicAdd(&as_[r1], sa1); atomicAdd(&ad_[r1], sd1); }
            }
        }
    }
}

// ---------------- pooling + MLP ----------------
__device__ __forceinline__ int lbound(const int* a, int n, int key) {
    int lo = 0, hi = n;
    while (lo < hi) {
        int mid = (lo + hi) >> 1;
        if (a[mid] < key) lo = mid + 1; else hi = mid;
    }
    return lo;
}

#define POOL_SPLIT 8
__global__ void pool_partial_kernel(const __half* __restrict__ x, const int* __restrict__ batch,
                                    float* __restrict__ pool) {
    int g = blockIdx.x / POOL_SPLIT;
    int part = blockIdx.x % POOL_SPLIT;
    int t = threadIdx.x;
    int lo = lbound(batch, NNODES, g);
    int hi = lbound(batch, NNODES, g + 1);
    int seg = hi - lo;
    int a = lo + (int)(((long long)seg * part) / POOL_SPLIT);
    int b = lo + (int)(((long long)seg * (part + 1)) / POOL_SPLIT);
    float acc = 0.f;
    for (int n = a; n < b; n++) acc += __half2float(x[(size_t)n * DMAX + t]);
    if (b > a) atomicAdd(&pool[g * DMAX + t], acc);
}

__global__ void mlp_kernel(const float* __restrict__ pool, const int* __restrict__ batch,
                           const float* __restrict__ fc1w, const float* __restrict__ fc1b,
                           const float* __restrict__ fc2w, const float* __restrict__ fc2b,
                           float* __restrict__ out) {
    __shared__ float gc[DMAX];
    __shared__ float hid[HID];
    __shared__ float red[256];
    int g = blockIdx.x;
    int t = threadIdx.x;
    int lo = lbound(batch, NNODES, g);
    int hi = lbound(batch, NNODES, g + 1);
    float cnt = fmaxf((float)(hi - lo), 1.f);
    gc[t] = pool[g * DMAX + t] / cnt;
    __syncthreads();
    for (int c = t; c < HID; c += 256) {
        float a = fc1b[c];
#pragma unroll 8
        for (int k = 0; k < DMAX; k++) a += gc[k] * fc1w[(size_t)k * HID + c];
        hid[c] = fmaxf(a, 0.f);
    }
    __syncthreads();
    float p = 0.f;
    for (int c = t; c < HID; c += 256) p += hid[c] * fc2w[c];
    red[t] = p;
    __syncthreads();
    for (int s = 128; s; s >>= 1) {
        if (t < s) red[t] += red[t + s];
        __syncthreads();
    }
    if (t == 0) out[g] = red[0] + fc2b[0];
}

// ---------------- launcher ----------------
extern "C" void kernel_launch(void* const* d_in, const int* in_sizes, int n_in,
                              void* d_out, int out_size) {
    const float* feature = (const float*)d_in[0];
    const int*   ei      = (const int*)d_in[1];
    const int*   batch   = (const int*)d_in[2];
    const float* W[3]    = {(const float*)d_in[3], (const float*)d_in[6], (const float*)d_in[9]};
    const float* att[3]  = {(const float*)d_in[4], (const float*)d_in[7], (const float*)d_in[10]};
    const float* bia[3]  = {(const float*)d_in[5], (const float*)d_in[8], (const float*)d_in[11]};
    const float* fc1w    = (const float*)d_in[12];
    const float* fc1b    = (const float*)d_in[13];
    const float* fc2w    = (const float*)d_in[14];
    const float* fc2b    = (const float*)d_in[15];

    float *asad, *wabuf, *wdbuf, *pool;
    __half *aggh, *xh, *fh, *x3h;
    int *csr, *cnt, *off, *cursor;
    cudaGetSymbolAddress((void**)&aggh, g_aggh);
    cudaGetSymbolAddress((void**)&x3h, g_x3h);
    cudaGetSymbolAddress((void**)&xh, g_xh);
    cudaGetSymbolAddress((void**)&fh, g_fh);
    cudaGetSymbolAddress((void**)&csr, g_csr);
    cudaGetSymbolAddress((void**)&cnt, g_cnt);
    cudaGetSymbolAddress((void**)&off, g_off);
    cudaGetSymbolAddress((void**)&cursor, g_cursor);
    cudaGetSymbolAddress((void**)&asad, g_asad);
    cudaGetSymbolAddress((void**)&wabuf, g_wa);
    cudaGetSymbolAddress((void**)&wdbuf, g_wd);
    cudaGetSymbolAddress((void**)&pool, g_pool);

    float* asbuf = asad;
    float* adbuf = asad + NNODES;

    // #1: wvec (+ zero cnt, pool)
    wvec_all_kernel<<<64, 256>>>(W[0], att[0], W[1], att[1], W[2], att[2],
                                 wabuf, wdbuf, cnt, pool);
    // #2: hist + layer-1 attdot + fp16 feature copy
    hist_attdot_kernel<<<HISTB + ATTB, 256>>>(ei, cnt, feature, wabuf, wdbuf,
                                              asbuf, adbuf, fh);
    // #3: scan
    scan_kernel<<<1, 1024>>>(cnt, off, cursor);
    // #4: csr fill
    csr_fill_kernel<<<HISTB, 256>>>(ei, cursor, csr);

    const int aggBlocks = ATTB;

    // #5: layer-1 aggregate  (profiled launch)
    gat_aggregate_kernel<64><<<aggBlocks, 256>>>(fh, asbuf, adbuf, off, csr, aggh);
    // #6: zero asad for layer-2 dots
    cudaMemsetAsync(asad, 0, 2 * NNODES * sizeof(float));
    // #7: gemm1 (64->64), fuse layer-2 dots
    h16_gemm_kernel<<<dim3((NNODES + TBM - 1) / TBM, 64 / TBN), 256>>>(
        aggh, W[0], bia[0], xh, NNODES, 64, 64,
        wabuf + 128, wdbuf + 128, asbuf, adbuf);

    // #8: layer-2 aggregate
    gat_aggregate_kernel<64><<<aggBlocks, 256>>>(xh, asbuf, adbuf, off, csr, aggh);
    // #9: zero asad for layer-3 dots
    cudaMemsetAsync(asad, 0, 2 * NNODES * sizeof(float));
    // #10: gemm2 (64->128), fuse layer-3 dots
    h16_gemm_kernel<<<dim3((NNODES + TBM - 1) / TBM, 128 / TBN), 256>>>(
        aggh, W[1], bia[1], xh, NNODES, 128, 64,
        wabuf + 256, wdbuf + 256, asbuf, adbuf);

    // #11: layer-3 aggregate
    gat_aggregate_kernel<128><<<aggBlocks, 256>>>(xh, asbuf, adbuf, off, csr, aggh);
    // #12: gemm3 (128->256)
    h16_gemm_kernel<<<dim3((NNODES + TBM - 1) / TBM, 256 / TBN), 256>>>(
        aggh, W[2], bia[2], x3h, NNODES, 256, 128,
        nullptr, nullptr, nullptr, nullptr);

    // #13: pool partials, #14: MLP
    pool_partial_kernel<<<NGRAPH * POOL_SPLIT, 256>>>(x3h, batch, pool);
    mlp_kernel<<<NGRAPH, 256>>>(pool, batch, fc1w, fc1b, fc2w, fc2b, (float*)d_out);
}

// round 15
// speedup vs baseline: 1.1371x; 1.0072x over previous
#include <cstdint>
#include <cuda_runtime.h>
#include <cuda_fp16.h>
#include <math_constants.h>

// Problem constants
#define NNODES 50000
#define NEDGES 800000
#define NEALL  (NEDGES + NNODES)   // edges + self loops
#define NGRAPH 64
#define DMAX   256
#define HID    512

// ---------------- scratch (no allocations allowed) ----------------
__device__ __half g_aggh[(size_t)NNODES * 128];  // aggregated x (fp16, pre-GEMM)
__device__ __half g_x3h[(size_t)NNODES * DMAX];  // layer-3 output (fp16, for pooling)
__device__ __half g_xh[(size_t)NNODES * 128];    // layer-1/2 outputs (fp16 gather operand)
__device__ __half g_fh[(size_t)NNODES * 64];     // fp16 copy of input features
__device__ int    g_csr[NEALL];                  // src node per CSR slot
__device__ int    g_cnt[NNODES];                 // in-degree
__device__ int    g_off[NNODES + 1];             // CSR offsets
__device__ int    g_cursor[NNODES];              // fill cursors
__device__ float  g_asad[2 * NNODES];            // [as | ad] combined (one memset)
__device__ float  g_wa[3 * 128];                 // W @ att_src per layer
__device__ float  g_wd[3 * 128];                 // W @ att_dst per layer
__device__ float  g_pool[NGRAPH * DMAX];         // pooled partial sums

// ---------------- wvec + zero(cnt,pool): launch #1 ----------------
__global__ void wvec_all_kernel(const float* __restrict__ W1, const float* __restrict__ a1,
                                const float* __restrict__ W2, const float* __restrict__ a2,
                                const float* __restrict__ W3, const float* __restrict__ a3,
                                float* __restrict__ wa, float* __restrict__ wd,
                                int* __restrict__ cnt, float* __restrict__ pool) {
    int gtid = blockIdx.x * 256 + threadIdx.x;   // 0..16383
    for (int i = gtid; i < NNODES; i += 64 * 256) cnt[i] = 0;
    for (int i = gtid; i < NGRAPH * DMAX; i += 64 * 256) pool[i] = 0.f;

    int w = gtid >> 5;
    int lane = threadIdx.x & 31;
    int l, idx;
    if (w < 128)      { l = 0; idx = w; }
    else if (w < 256) { l = 1; idx = w - 128; }
    else if (w < 512) { l = 2; idx = w - 256; }
    else return;
    const float* W = (l == 0) ? W1 : (l == 1) ? W2 : W3;
    const float* att = (l == 0) ? a1 : (l == 1) ? a2 : a3;
    int Din = (l == 2) ? 128 : 64;
    int Dout = (l == 0) ? 64 : (l == 1) ? 128 : 256;
    int which = (idx >= Din) ? 1 : 0;
    int i = idx - which * Din;
    const float* attp = att + which * Dout;
    const float* Wr = W + (size_t)i * Dout;
    float acc = 0.f;
    for (int d = lane; d < Dout; d += 32) acc += Wr[d] * attp[d];
#pragma unroll
    for (int o = 16; o; o >>= 1) acc += __shfl_xor_sync(0xffffffffu, acc, o);
    if (lane == 0) {
        if (which == 0) wa[l * 128 + i] = acc;
        else            wd[l * 128 + i] = acc;
    }
}

// ---------------- hist + layer-1 attdot + fp16 feature copy: launch #2 ----------------
#define HISTB ((NEALL + 255) / 256)       // 3321 blocks for hist
#define ATTB  ((NNODES * 32 + 255) / 256) // 6250 blocks for attdot
__global__ void hist_attdot_kernel(const int* __restrict__ ei, int* __restrict__ cnt,
                                   const float* __restrict__ x, const float* __restrict__ wa,
                                   const float* __restrict__ wd,
                                   float* __restrict__ as_, float* __restrict__ ad_,
                                   __half* __restrict__ xh) {
    if (blockIdx.x < HISTB) {
        int e = blockIdx.x * 256 + threadIdx.x;
        if (e >= NEALL) return;
        int d = (e < NEDGES) ? ei[NEDGES + e] : (e - NEDGES);
        atomicAdd(&cnt[d], 1);
    } else {
        int w = ((blockIdx.x - HISTB) * 256 + threadIdx.x) >> 5;
        int lane = threadIdx.x & 31;
        if (w >= NNODES) return;
        float2 xv = *(const float2*)(x + (size_t)w * 64 + 2 * lane);
        float a0 = xv.x * wa[2 * lane] + xv.y * wa[2 * lane + 1];
        float a1 = xv.x * wd[2 * lane] + xv.y * wd[2 * lane + 1];
        *(__half2*)(xh + (size_t)w * 64 + 2 * lane) = __floats2half2_rn(xv.x, xv.y);
#pragma unroll
        for (int o = 16; o; o >>= 1) {
            a0 += __shfl_xor_sync(0xffffffffu, a0, o);
            a1 += __shfl_xor_sync(0xffffffffu, a1, o);
        }
        if (lane == 0) { as_[w] = a0; ad_[w] = a1; }
    }
}

// ---------------- scan: launch #3 ----------------
__global__ __launch_bounds__(1024) void scan_kernel(const int* __restrict__ cnt,
                                                    int* __restrict__ off,
                                                    int* __restrict__ cursor) {
    __shared__ int wsums[32];
    const int t = threadIdx.x;
    const int PER = (NNODES + 1023) / 1024;   // 49
    int b0 = t * PER;
    int b1 = b0 + PER; if (b1 > NNODES) b1 = NNODES;
    int s = 0;
    for (int i = b0; i < b1; i++) s += cnt[i];
    int v = s;
#pragma unroll
    for (int o = 1; o < 32; o <<= 1) {
        int n = __shfl_up_sync(0xffffffffu, v, o);
        if ((t & 31) >= o) v += n;
    }
    if ((t & 31) == 31) wsums[t >> 5] = v;
    __syncthreads();
    if (t < 32) {
        int w = wsums[t];
#pragma unroll
        for (int o = 1; o < 32; o <<= 1) {
            int n = __shfl_up_sync(0xffffffffu, w, o);
            if (t >= o) w += n;
        }
        wsums[t] = w;
    }
    __syncthreads();
    int excl = v - s + ((t >= 32) ? wsums[(t >> 5) - 1] : 0);
    int run = excl;
    for (int i = b0; i < b1; i++) {
        off[i] = run;
        cursor[i] = run;
        run += cnt[i];
    }
    if (t == 0) off[NNODES] = NEALL;
}

// ---------------- csr fill: launch #4 ----------------
__global__ void csr_fill_kernel(const int* __restrict__ ei, int* __restrict__ cursor,
                                int* __restrict__ csr) {
    int e = blockIdx.x * blockDim.x + threadIdx.x;
    if (e >= NEALL) return;
    int s, d;
    if (e < NEDGES) { s = ei[e]; d = ei[NEDGES + e]; }
    else            { s = d = e - NEDGES; }
    int pos = atomicAdd(&cursor[d], 1);
    csr[pos] = s;
}

// ---------------- fused GAT aggregation (fp16 in, fp16 out) ----------------
// warp per dst node; NEDG=4 edges in flight, LPG=8 lanes per edge,
// each lane covers D/8 halves = VEC uint4 loads (VEC = D/64, 16B each).
// 8 lanes x 16B = 128B contiguous per load instruction (full coalescing).
template <int D>
__global__ __launch_bounds__(256) void gat_aggregate_kernel(
    const __half* __restrict__ x, const float* __restrict__ as_,
    const float* __restrict__ ad_, const int* __restrict__ off,
    const int* __restrict__ csr, __half* __restrict__ out) {
    int w = (blockIdx.x * blockDim.x + threadIdx.x) >> 5;
    int lane = threadIdx.x & 31;
    if (w >= NNODES) return;
    int lo = off[w], hi = off[w + 1];
    float adv = ad_[w];

    // pass 1: segment max of leaky_relu(as[src]+ad[dst])
    float mx = -CUDART_INF_F;
    for (int e = lo + lane; e < hi; e += 32) {
        float v = as_[csr[e]] + adv;
        v = (v > 0.f) ? v : 0.2f * v;
        mx = fmaxf(mx, v);
    }
#pragma unroll
    for (int o = 16; o; o >>= 1) mx = fmaxf(mx, __shfl_xor_sync(0xffffffffu, mx, o));

    // pass 2
    constexpr int NEDG = 4;
    constexpr int LPG  = 8;
    constexpr int VEC  = D / 64;          // uint4 loads per lane (1 or 2)
    const int sub = lane / LPG;
    const int sl  = lane % LPG;

    float2 acc[4 * VEC];
#pragma unroll
    for (int k = 0; k < 4 * VEC; k++) acc[k] = make_float2(0.f, 0.f);
    float ssum = 0.f;

    for (int e0 = lo; e0 < hi; e0 += NEDG) {
        int e = e0 + sub;
        bool valid = (e < hi);
        int s = valid ? csr[e] : 0;
        float wgt = 0.f;
        if (valid) {
            float v = as_[s] + adv;
            v = (v > 0.f) ? v : 0.2f * v;
            wgt = __expf(v - mx);
        }
        ssum += wgt;
        if (valid) {
            const uint4* xp = (const uint4*)(x + (size_t)s * D + sl * (8 * VEC));
#pragma unroll
            for (int vv = 0; vv < VEC; vv++) {
                uint4 raw = xp[vv];
                const __half2* hp = (const __half2*)&raw;
#pragma unroll
                for (int k = 0; k < 4; k++) {
                    float2 f = __half22float2(hp[k]);
                    acc[vv * 4 + k].x += wgt * f.x;
                    acc[vv * 4 + k].y += wgt * f.y;
                }
            }
        }
    }

    // combine sub-groups (identical feature positions)
#pragma unroll
    for (int o = LPG; o < 32; o <<= 1) {
        ssum += __shfl_xor_sync(0xffffffffu, ssum, o);
#pragma unroll
        for (int k = 0; k < 4 * VEC; k++) {
            acc[k].x += __shfl_xor_sync(0xffffffffu, acc[k].x, o);
            acc[k].y += __shfl_xor_sync(0xffffffffu, acc[k].y, o);
        }
    }

    if (sub == 0) {
        float inv = 1.f / ssum;
#pragma unroll
        for (int vv = 0; vv < VEC; vv++) {
            __half2 r[4];
#pragma unroll
            for (int k = 0; k < 4; k++)
                r[k] = __floats2half2_rn(acc[vv * 4 + k].x * inv, acc[vv * 4 + k].y * inv);
            *(uint4*)(out + (size_t)w * D + sl * (8 * VEC) + 8 * vv) = *(const uint4*)r;
        }
    }
}

// ---------------- FP16 tensor-core GEMM: relu(A @ B + bias) ----------------
__device__ __forceinline__ void mma_f16(float* c, const uint32_t* a, const uint32_t* b) {
    asm volatile("mma.sync.aligned.m16n8k16.row.col.f32.f16.f16.f32 "
                 "{%0,%1,%2,%3}, {%4,%5,%6,%7}, {%8,%9}, {%0,%1,%2,%3};"
                 : "+f"(c[0]), "+f"(c[1]), "+f"(c[2]), "+f"(c[3])
                 : "r"(a[0]), "r"(a[1]), "r"(a[2]), "r"(a[3]), "r"(b[0]), "r"(b[1]));
}

#define TBM 128
#define TBN 64
#define TBK 32
#define TKP (TBK + 8)   // padded row stride in halves (80B, 16B-aligned)

__global__ __launch_bounds__(256) void h16_gemm_kernel(const __half* __restrict__ A,
                                                       const float* __restrict__ B,
                                                       const float* __restrict__ bias,
                                                       __half* __restrict__ Ch,
                                                       int M, int N, int K,
                                                       const float* __restrict__ wa_next,
                                                       const float* __restrict__ wd_next,
                                                       float* __restrict__ as_,
                                                       float* __restrict__ ad_) {
    __shared__ __half As[TBM][TKP];   // row-major [m][k]
    __shared__ __half Bs[TBN][TKP];   // n-major  [n][k]
    const int tid = threadIdx.x;
    const int warp = tid >> 5, lane = tid & 31;
    const int g = lane >> 2, q = lane & 3;
    const int m0 = (warp >> 1) * 32;
    const int n0 = (warp & 1) * 32;
    const int row0 = blockIdx.x * TBM;
    const int col0 = blockIdx.y * TBN;

    float acc[2][4][4];
#pragma unroll
    for (int mt = 0; mt < 2; mt++)
#pragma unroll
        for (int nt = 0; nt < 4; nt++)
#pragma unroll
            for (int i = 0; i < 4; i++) acc[mt][nt][i] = 0.f;

    for (int k0 = 0; k0 < K; k0 += TBK) {
#pragma unroll
        for (int i = 0; i < 2; i++) {
            int linear = tid + 256 * i;
            int ar = linear >> 2;
            int ac = (linear & 3) << 3;
            int grow = row0 + ar;
            uint4 v = make_uint4(0u, 0u, 0u, 0u);
            if (grow < M) v = *(const uint4*)(A + (size_t)grow * K + k0 + ac);
            *(uint4*)&As[ar][ac] = v;
        }
#pragma unroll
        for (int i = 0; i < 2; i++) {
            int linear = tid + 256 * i;
            int bk = linear >> 4;
            int bn = (linear & 15) << 2;
            float4 v = *(const float4*)(B + (size_t)(k0 + bk) * N + col0 + bn);
            Bs[bn + 0][bk] = __float2half_rn(v.x);
            Bs[bn + 1][bk] = __float2half_rn(v.y);
            Bs[bn + 2][bk] = __float2half_rn(v.z);
            Bs[bn + 3][bk] = __float2half_rn(v.w);
        }
        __syncthreads();
#pragma unroll
        for (int ks = 0; ks < TBK; ks += 16) {
            uint32_t af[2][4], bf[4][2];
#pragma unroll
            for (int mt = 0; mt < 2; mt++) {
                int mb = m0 + mt * 16;
                af[mt][0] = *(const uint32_t*)&As[mb + g][ks + 2 * q];
                af[mt][1] = *(const uint32_t*)&As[mb + 8 + g][ks + 2 * q];
                af[mt][2] = *(const uint32_t*)&As[mb + g][ks + 2 * q + 8];
                af[mt][3] = *(const uint32_t*)&As[mb + 8 + g][ks + 2 * q + 8];
            }
#pragma unroll
            for (int nt = 0; nt < 4; nt++) {
                int nb = n0 + nt * 8 + g;
                bf[nt][0] = *(const uint32_t*)&Bs[nb][ks + 2 * q];
                bf[nt][1] = *(const uint32_t*)&Bs[nb][ks + 2 * q + 8];
            }
#pragma unroll
            for (int mt = 0; mt < 2; mt++)
#pragma unroll
                for (int nt = 0; nt < 4; nt++)
                    mma_f16(acc[mt][nt], af[mt], bf[nt]);
        }
        __syncthreads();
    }

    // epilogue: bias + relu + fp16 store + optional fused attention dots
#pragma unroll
    for (int mt = 0; mt < 2; mt++) {
        int r0 = row0 + m0 + mt * 16 + g;
        int r1 = r0 + 8;
        float sa0 = 0.f, sd0 = 0.f, sa1 = 0.f, sd1 = 0.f;
#pragma unroll
        for (int nt = 0; nt < 4; nt++) {
            int col = col0 + n0 + nt * 8 + 2 * q;
            float b0 = bias[col], b1 = bias[col + 1];
            float v00 = fmaxf(acc[mt][nt][0] + b0, 0.f);
            float v01 = fmaxf(acc[mt][nt][1] + b1, 0.f);
            float v10 = fmaxf(acc[mt][nt][2] + b0, 0.f);
            float v11 = fmaxf(acc[mt][nt][3] + b1, 0.f);
            if (r0 < M) *(__half2*)(Ch + (size_t)r0 * N + col) = __floats2half2_rn(v00, v01);
            if (r1 < M) *(__half2*)(Ch + (size_t)r1 * N + col) = __floats2half2_rn(v10, v11);
            if (wa_next) {
                float wa0 = wa_next[col], wa1 = wa_next[col + 1];
                float wd0 = wd_next[col], wd1 = wd_next[col + 1];
                sa0 += v00 * wa0 + v01 * wa1;
                sd0 += v00 * wd0 + v01 * wd1;
                sa1 += v10 * wa0 + v11 * wa1;
                sd1 += v10 * wd0 + v11 * wd1;
            }
        }
        if (wa_next) {
#pragma unroll
            for (int o = 1; o < 4; o <<= 1) {
                sa0 += __shfl_xor_sync(0xffffffffu, sa0, o);
                sd0 += __shfl_xor_sync(0xffffffffu, sd0, o);
                sa1 += __shfl_xor_sync(0xffffffffu, sa1, o);
                sd1 += __shfl_xor_sync(0xffffffffu, sd1, o);
            }
            if (q == 0) {
                if (r0 < M) { atomicAdd(&as_[r0], sa0); atomicAdd(&ad_[r0], sd0); }
                if (r1 < M) { atomicAdd(&as_[r1], sa1); atomicAdd(&ad_[r1], sd1); }
            }
        }
    }
}

// ---------------- pooling + MLP ----------------
__device__ __forceinline__ int lbound(const int* a, int n, int key) {
    int lo = 0, hi = n;
    while (lo < hi) {
        int mid = (lo + hi) >> 1;
        if (a[mid] < key) lo = mid + 1; else hi = mid;
    }
    return lo;
}

#define POOL_SPLIT 8
__global__ void pool_partial_kernel(const __half* __restrict__ x, const int* __restrict__ batch,
                                    float* __restrict__ pool) {
    int g = blockIdx.x / POOL_SPLIT;
    int part = blockIdx.x % POOL_SPLIT;
    int t = threadIdx.x;
    int lo = lbound(batch, NNODES, g);
    int hi = lbound(batch, NNODES, g + 1);
    int seg = hi - lo;
    int a = lo + (int)(((long long)seg * part) / POOL_SPLIT);
    int b = lo + (int)(((long long)seg * (part + 1)) / POOL_SPLIT);
    float acc = 0.f;
    for (int n = a; n < b; n++) acc += __half2float(x[(size_t)n * DMAX + t]);
    if (b > a) atomicAdd(&pool[g * DMAX + t], acc);
}

__global__ void mlp_kernel(const float* __restrict__ pool, const int* __restrict__ batch,
                           const float* __restrict__ fc1w, const float* __restrict__ fc1b,
                           const float* __restrict__ fc2w, const float* __restrict__ fc2b,
                           float* __restrict__ out) {
    __shared__ float gc[DMAX];
    __shared__ float hid[HID];
    __shared__ float red[256];
    int g = blockIdx.x;
    int t = threadIdx.x;
    int lo = lbound(batch, NNODES, g);
    int hi = lbound(batch, NNODES, g + 1);
    float cnt = fmaxf((float)(hi - lo), 1.f);
    gc[t] = pool[g * DMAX + t] / cnt;
    __syncthreads();
    for (int c = t; c < HID; c += 256) {
        float a = fc1b[c];
#pragma unroll 8
        for (int k = 0; k < DMAX; k++) a += gc[k] * fc1w[(size_t)k * HID + c];
        hid[c] = fmaxf(a, 0.f);
    }
    __syncthreads();
    float p = 0.f;
    for (int c = t; c < HID; c += 256) p += hid[c] * fc2w[c];
    red[t] = p;
    __syncthreads();
    for (int s = 128; s; s >>= 1) {
        if (t < s) red[t] += red[t + s];
        __syncthreads();
    }
    if (t == 0) out[g] = red[0] + fc2b[0];
}

// ---------------- launcher ----------------
extern "C" void kernel_launch(void* const* d_in, const int* in_sizes, int n_in,
                              void* d_out, int out_size) {
    const float* feature = (const float*)d_in[0];
    const int*   ei      = (const int*)d_in[1];
    const int*   batch   = (const int*)d_in[2];
    const float* W[3]    = {(const float*)d_in[3], (const float*)d_in[6], (const float*)d_in[9]};
    const float* att[3]  = {(const float*)d_in[4], (const float*)d_in[7], (const float*)d_in[10]};
    const float* bia[3]  = {(const float*)d_in[5], (const float*)d_in[8], (const float*)d_in[11]};
    const float* fc1w    = (const float*)d_in[12];
    const float* fc1b    = (const float*)d_in[13];
    const float* fc2w    = (const float*)d_in[14];
    const float* fc2b    = (const float*)d_in[15];

    float *asad, *wabuf, *wdbuf, *pool;
    __half *aggh, *xh, *fh, *x3h;
    int *csr, *cnt, *off, *cursor;
    cudaGetSymbolAddress((void**)&aggh, g_aggh);
    cudaGetSymbolAddress((void**)&x3h, g_x3h);
    cudaGetSymbolAddress((void**)&xh, g_xh);
    cudaGetSymbolAddress((void**)&fh, g_fh);
    cudaGetSymbolAddress((void**)&csr, g_csr);
    cudaGetSymbolAddress((void**)&cnt, g_cnt);
    cudaGetSymbolAddress((void**)&off, g_off);
    cudaGetSymbolAddress((void**)&cursor, g_cursor);
    cudaGetSymbolAddress((void**)&asad, g_asad);
    cudaGetSymbolAddress((void**)&wabuf, g_wa);
    cudaGetSymbolAddress((void**)&wdbuf, g_wd);
    cudaGetSymbolAddress((void**)&pool, g_pool);

    float* asbuf = asad;
    float* adbuf = asad + NNODES;

    // #1: wvec (+ zero cnt, pool)
    wvec_all_kernel<<<64, 256>>>(W[0], att[0], W[1], att[1], W[2], att[2],
                                 wabuf, wdbuf, cnt, pool);
    // #2: hist + layer-1 attdot + fp16 feature copy
    hist_attdot_kernel<<<HISTB + ATTB, 256>>>(ei, cnt, feature, wabuf, wdbuf,
                                              asbuf, adbuf, fh);
    // #3: scan
    scan_kernel<<<1, 1024>>>(cnt, off, cursor);
    // #4: csr fill
    csr_fill_kernel<<<HISTB, 256>>>(ei, cursor, csr);

    const int aggBlocks = ATTB;

    // #5: layer-1 aggregate
    gat_aggregate_kernel<64><<<aggBlocks, 256>>>(fh, asbuf, adbuf, off, csr, aggh);
    // #6: zero asad for layer-2 dots
    cudaMemsetAsync(asad, 0, 2 * NNODES * sizeof(float));
    // #7: gemm1 (64->64), fuse layer-2 dots
    h16_gemm_kernel<<<dim3((NNODES + TBM - 1) / TBM, 64 / TBN), 256>>>(
        aggh, W[0], bia[0], xh, NNODES, 64, 64,
        wabuf + 128, wdbuf + 128, asbuf, adbuf);

    // #8: layer-2 aggregate
    gat_aggregate_kernel<64><<<aggBlocks, 256>>>(xh, asbuf, adbuf, off, csr, aggh);
    // #9: zero asad for layer-3 dots
    cudaMemsetAsync(asad, 0, 2 * NNODES * sizeof(float));
    // #10: gemm2 (64->128), fuse layer-3 dots
    h16_gemm_kernel<<<dim3((NNODES + TBM - 1) / TBM, 128 / TBN), 256>>>(
        aggh, W[1], bia[1], xh, NNODES, 128, 64,
        wabuf + 256, wdbuf + 256, asbuf, adbuf);

    // #11: layer-3 aggregate (NEDG=4 now)
    gat_aggregate_kernel<128><<<aggBlocks, 256>>>(xh, asbuf, adbuf, off, csr, aggh);
    // #12: gemm3 (128->256)
    h16_gemm_kernel<<<dim3((NNODES + TBM - 1) / TBM, 256 / TBN), 256>>>(
        aggh, W[2], bia[2], x3h, NNODES, 256, 128,
        nullptr, nullptr, nullptr, nullptr);

    // #13: pool partials, #14: MLP
    pool_partial_kernel<<<NGRAPH * POOL_SPLIT, 256>>>(x3h, batch, pool);
    mlp_kernel<<<NGRAPH, 256>>>(pool, batch, fc1w, fc1b, fc2w, fc2b, (float*)d_out);
}